// round 10
// baseline (speedup 1.0000x reference)
// R10: held stable — tenth consecutive broker timeout, zero measurements all
// session. Audited fp32 baseline at its computable FFMA operating point;
// source diff-checked intact. First real bench (4.0-5.5 ms predicted) gates
// the tcgen05 port.
#include <cuda_runtime.h>

#define BATCH   4
#define SEQ     2048
#define DMODEL  1024
#define NHEAD   16
#define DK      64
#define MTOT    (BATCH * SEQ)   // 8192

// Scratch (device globals: allocation-free rule)
__device__ float g_Q[(size_t)BATCH * NHEAD * SEQ * DK];   // [b,h,s,d]
__device__ float g_K[(size_t)BATCH * NHEAD * SEQ * DK];
__device__ float g_V[(size_t)BATCH * NHEAD * SEQ * DK];
__device__ float g_O[(size_t)MTOT * DMODEL];              // [b,s,h*64+d]

// ---------------------------------------------------------------------------
// Shared NT SGEMM tile: C[128x128] = A[128xK] * B[128xK]^T, K=1024.
// Both operands K-major (row-major [rows, 1024]). 256 threads, 8x8 frags,
// interleaved tiling: m = i*16+ty, n = j*16+tx.
// Register-prefetch double buffering: global loads for K-tile t+1 issue
// before the FFMA block for tile t, hiding L2/DRAM latency.
// ---------------------------------------------------------------------------
__device__ __forceinline__ void gemm_nt_128(const float* __restrict__ A,
                                            const float* __restrict__ B,
                                            float (&acc)[8][8])
{
    const int tid = threadIdx.x;
    __shared__ float As[128][36];   // pad 4: 144B row stride, 16B aligned
    __shared__ float Bs[128][36];

    const float* Ablk = A + (size_t)blockIdx.y * 128 * DMODEL;
    const float* Bblk = B + (size_t)blockIdx.x * 128 * DMODEL;
    const int tx = tid & 15, ty = tid >> 4;

    float4 pa[4], pb[4];

    // Prefetch K-tile 0
#pragma unroll
    for (int t = 0; t < 4; t++) {
        int idx = tid + t * 256;           // 0..1023 float4 slots
        int row = idx >> 3;                // 0..127
        int kq  = (idx & 7) * 4;           // 0..28
        pa[t] = *reinterpret_cast<const float4*>(Ablk + (size_t)row * DMODEL + kq);
        pb[t] = *reinterpret_cast<const float4*>(Bblk + (size_t)row * DMODEL + kq);
    }

    for (int k0 = 0; k0 < DMODEL; k0 += 32) {
        // Commit prefetched tile to smem
#pragma unroll
        for (int t = 0; t < 4; t++) {
            int idx = tid + t * 256;
            int row = idx >> 3;
            int kq  = (idx & 7) * 4;
            *reinterpret_cast<float4*>(&As[row][kq]) = pa[t];
            *reinterpret_cast<float4*>(&Bs[row][kq]) = pb[t];
        }
        __syncthreads();

        // Issue next tile's global loads (latency hidden behind FFMAs)
        if (k0 + 32 < DMODEL) {
#pragma unroll
            for (int t = 0; t < 4; t++) {
                int idx = tid + t * 256;
                int row = idx >> 3;
                int kq  = (idx & 7) * 4;
                pa[t] = *reinterpret_cast<const float4*>(Ablk + (size_t)row * DMODEL + k0 + 32 + kq);
                pb[t] = *reinterpret_cast<const float4*>(Bblk + (size_t)row * DMODEL + k0 + 32 + kq);
            }
        }

#pragma unroll
        for (int kk = 0; kk < 32; kk++) {
            float a[8], b[8];
#pragma unroll
            for (int i = 0; i < 8; i++) a[i] = As[i * 16 + ty][kk];
#pragma unroll
            for (int j = 0; j < 8; j++) b[j] = Bs[j * 16 + tx][kk];
#pragma unroll
            for (int i = 0; i < 8; i++)
#pragma unroll
                for (int j = 0; j < 8; j++)
                    acc[i][j] = fmaf(a[i], b[j], acc[i][j]);
        }
        __syncthreads();
    }
}

// ---------------------------------------------------------------------------
// Fused QKV projection: z in {0,1,2} selects Q/K/V. Output remapped to
// [b, h, s, d] layout for the attention kernel.
// ---------------------------------------------------------------------------
__global__ __launch_bounds__(256, 2)
void qkv_proj_kernel(const float* __restrict__ x,
                     const float* __restrict__ Wq, const float* __restrict__ bq,
                     const float* __restrict__ Wk, const float* __restrict__ bk,
                     const float* __restrict__ Wv, const float* __restrict__ bv)
{
    const int z = blockIdx.z;
    const float* W    = (z == 0) ? Wq : ((z == 1) ? Wk : Wv);
    const float* bias = (z == 0) ? bq : ((z == 1) ? bk : bv);
    float* out        = (z == 0) ? g_Q : ((z == 1) ? g_K : g_V);

    float acc[8][8] = {};
    gemm_nt_128(x, W, acc);

    const int tx = threadIdx.x & 15, ty = threadIdx.x >> 4;
#pragma unroll
    for (int i = 0; i < 8; i++) {
        int m = blockIdx.y * 128 + i * 16 + ty;   // b*2048 + s
        int b = m >> 11, s = m & 2047;
#pragma unroll
        for (int j = 0; j < 8; j++) {
            int n = blockIdx.x * 128 + j * 16 + tx;  // h*64 + d
            int h = n >> 6, d = n & 63;
            out[(((size_t)(b * NHEAD + h) * SEQ) + s) * DK + d] = acc[i][j] + bias[n];
        }
    }
}

// ---------------------------------------------------------------------------
// Output projection: d_out = g_O @ Wo^T + bo
// ---------------------------------------------------------------------------
__global__ __launch_bounds__(256, 2)
void out_proj_kernel(const float* __restrict__ Wo, const float* __restrict__ bo,
                     float* __restrict__ out)
{
    float acc[8][8] = {};
    gemm_nt_128(g_O, Wo, acc);

    const int tx = threadIdx.x & 15, ty = threadIdx.x >> 4;
#pragma unroll
    for (int i = 0; i < 8; i++) {
        int m = blockIdx.y * 128 + i * 16 + ty;
#pragma unroll
        for (int j = 0; j < 8; j++) {
            int n = blockIdx.x * 128 + j * 16 + tx;
            out[(size_t)m * DMODEL + n] = acc[i][j] + bo[n];
        }
    }
}

// ---------------------------------------------------------------------------
// Flash attention (fp32, online softmax). One block = 64 query rows of one
// (b,h). Key loop in tiles of 32. 256 threads: 16x16.
//   S-frag: rows i*16+ty (i<4), cols {tx, 16+tx}.
//   O-frag: rows i*16+ty (i<4), cols tx*4..tx*4+3  (consecutive d -> LDS.128
//           V operand reads and STG.128 output stores).
// Q is pre-scaled by 1/sqrt(dk)=0.125 (power of two -> exact; scores are
// bit-identical to post-scaling) so the softmax path has no per-element FMUL.
// Row r is owned by the 16 lanes sharing ty == r%16 (half-warp -> shfl w16).
// K/V tile loads register-prefetched one iteration ahead.
// ---------------------------------------------------------------------------
__global__ __launch_bounds__(256)
void attn_kernel()
{
    const int bh = blockIdx.y;            // b*16 + h
    const int q0 = blockIdx.x * 64;
    const float* Qp = g_Q + (size_t)bh * SEQ * DK;
    const float* Kp = g_K + (size_t)bh * SEQ * DK;
    const float* Vp = g_V + (size_t)bh * SEQ * DK;

    __shared__ float Qs[64][64];   // 256B rows, 16B aligned
    __shared__ float Ks[32][68];   // 272B rows, 16B aligned (pad 4)
    __shared__ float Vs[32][64];   // float4 reads at [kk][tx*4]: conflict-free
    __shared__ float Ps[64][32];   // 128B rows

    const int tid = threadIdx.x;
    const int tx = tid & 15, ty = tid >> 4;

    // Load the Q tile once (64x64 = 1024 float4), pre-scaled by 0.125 (exact)
#pragma unroll
    for (int t = 0; t < 4; t++) {
        int idx = tid + t * 256;
        int row = idx >> 4, cq = (idx & 15) * 4;
        float4 q = *reinterpret_cast<const float4*>(Qp + (size_t)(q0 + row) * DK + cq);
        q.x *= 0.125f; q.y *= 0.125f; q.z *= 0.125f; q.w *= 0.125f;
        *reinterpret_cast<float4*>(&Qs[row][cq]) = q;
    }

    float m_i[4], l_i[4], o[4][4];
#pragma unroll
    for (int i = 0; i < 4; i++) {
        m_i[i] = -1e30f; l_i[i] = 0.0f;
#pragma unroll
        for (int j = 0; j < 4; j++) o[i][j] = 0.0f;
    }

    // Prefetch K/V tile 0 into registers
    float4 pk[2], pv[2];
#pragma unroll
    for (int t = 0; t < 2; t++) {
        int idx = tid + t * 256;
        int row = idx >> 4, cq = (idx & 15) * 4;
        pk[t] = *reinterpret_cast<const float4*>(Kp + (size_t)row * DK + cq);
        pv[t] = *reinterpret_cast<const float4*>(Vp + (size_t)row * DK + cq);
    }

    for (int kt = 0; kt < SEQ; kt += 32) {
        __syncthreads();   // previous O-GEMM done reading Vs/Ps before overwrite
#pragma unroll
        for (int t = 0; t < 2; t++) {
            int idx = tid + t * 256;
            int row = idx >> 4, cq = (idx & 15) * 4;
            *reinterpret_cast<float4*>(&Ks[row][cq]) = pk[t];
            *reinterpret_cast<float4*>(&Vs[row][cq]) = pv[t];
        }
        __syncthreads();

        // Prefetch next tile while S-GEMM runs
        if (kt + 32 < SEQ) {
#pragma unroll
            for (int t = 0; t < 2; t++) {
                int idx = tid + t * 256;
                int row = idx >> 4, cq = (idx & 15) * 4;
                pk[t] = *reinterpret_cast<const float4*>(Kp + (size_t)(kt + 32 + row) * DK + cq);
                pv[t] = *reinterpret_cast<const float4*>(Vp + (size_t)(kt + 32 + row) * DK + cq);
            }
        }

        // S = (Q/8) @ K^T for this 64x32 tile — LDS.128 over kk
        float s[4][2];
#pragma unroll
        for (int i = 0; i < 4; i++) { s[i][0] = 0.0f; s[i][1] = 0.0f; }
#pragma unroll
        for (int kk = 0; kk < 64; kk += 4) {
            float4 b0 = *reinterpret_cast<const float4*>(&Ks[tx][kk]);
            float4 b1 = *reinterpret_cast<const float4*>(&Ks[16 + tx][kk]);
#pragma unroll
            for (int i = 0; i < 4; i++) {
                float4 a = *reinterpret_cast<const float4*>(&Qs[i * 16 + ty][kk]);
                s[i][0] = fmaf(a.x, b0.x, s[i][0]);
                s[i][0] = fmaf(a.y, b0.y, s[i][0]);
                s[i][0] = fmaf(a.z, b0.z, s[i][0]);
                s[i][0] = fmaf(a.w, b0.w, s[i][0]);
                s[i][1] = fmaf(a.x, b1.x, s[i][1]);
                s[i][1] = fmaf(a.y, b1.y, s[i][1]);
                s[i][1] = fmaf(a.z, b1.z, s[i][1]);
                s[i][1] = fmaf(a.w, b1.w, s[i][1]);
            }
        }

        // Online softmax update (rows spread over 16 lanes, shfl width 16)
#pragma unroll
        for (int i = 0; i < 4; i++) {
            float s0 = s[i][0];
            float s1 = s[i][1];
            float rm = fmaxf(s0, s1);
#pragma unroll
            for (int off = 1; off < 16; off <<= 1)
                rm = fmaxf(rm, __shfl_xor_sync(0xffffffffu, rm, off, 16));
            float mn = fmaxf(m_i[i], rm);
            float corr = __expf(m_i[i] - mn);
            float p0 = __expf(s0 - mn);
            float p1 = __expf(s1 - mn);
            float rs = p0 + p1;
#pragma unroll
            for (int off = 1; off < 16; off <<= 1)
                rs += __shfl_xor_sync(0xffffffffu, rs, off, 16);
            l_i[i] = l_i[i] * corr + rs;
            m_i[i] = mn;
#pragma unroll
            for (int j = 0; j < 4; j++) o[i][j] *= corr;
            Ps[i * 16 + ty][tx]      = p0;
            Ps[i * 16 + ty][16 + tx] = p1;
        }
        __syncthreads();

        // O += P @ V — both operands read with LDS.128 (8 LDS per 64 FFMA)
#pragma unroll
        for (int kk4 = 0; kk4 < 32; kk4 += 4) {
            float4 p4[4];
#pragma unroll
            for (int i = 0; i < 4; i++)
                p4[i] = *reinterpret_cast<const float4*>(&Ps[i * 16 + ty][kk4]);
#pragma unroll
            for (int u = 0; u < 4; u++) {
                float4 v4 = *reinterpret_cast<const float4*>(&Vs[kk4 + u][tx * 4]);
                float p[4] = {
                    reinterpret_cast<const float*>(&p4[0])[u],
                    reinterpret_cast<const float*>(&p4[1])[u],
                    reinterpret_cast<const float*>(&p4[2])[u],
                    reinterpret_cast<const float*>(&p4[3])[u]
                };
#pragma unroll
                for (int i = 0; i < 4; i++) {
                    o[i][0] = fmaf(p[i], v4.x, o[i][0]);
                    o[i][1] = fmaf(p[i], v4.y, o[i][1]);
                    o[i][2] = fmaf(p[i], v4.z, o[i][2]);
                    o[i][3] = fmaf(p[i], v4.w, o[i][3]);
                }
            }
        }
    }

    // Normalize and write to [b, s, h*64+d]; O-frag cols tx*4..tx*4+3 are
    // consecutive -> one STG.128 per row-frag.
    const int b = bh >> 4, h = bh & 15;
#pragma unroll
    for (int i = 0; i < 4; i++) {
        float inv = 1.0f / l_i[i];
        int srow = q0 + i * 16 + ty;
        float4 val = make_float4(o[i][0] * inv, o[i][1] * inv,
                                 o[i][2] * inv, o[i][3] * inv);
        *reinterpret_cast<float4*>(
            &g_O[((size_t)(b * SEQ + srow)) * DMODEL + h * DK + tx * 4]) = val;
    }
}

// ---------------------------------------------------------------------------
extern "C" void kernel_launch(void* const* d_in, const int* in_sizes, int n_in,
                              void* d_out, int out_size)
{
    const float* x  = (const float*)d_in[0];
    const float* Wq = (const float*)d_in[1];
    const float* bq = (const float*)d_in[2];
    const float* Wk = (const float*)d_in[3];
    const float* bk = (const float*)d_in[4];
    const float* Wv = (const float*)d_in[5];
    const float* bv = (const float*)d_in[6];
    const float* Wo = (const float*)d_in[7];
    const float* bo = (const float*)d_in[8];
    float* out = (float*)d_out;

    dim3 gQKV(DMODEL / 128, MTOT / 128, 3);        // (8, 64, 3)
    qkv_proj_kernel<<<gQKV, 256>>>(x, Wq, bq, Wk, bk, Wv, bv);

    dim3 gAttn(SEQ / 64, BATCH * NHEAD);           // (32, 64)
    attn_kernel<<<gAttn, 256>>>();

    dim3 gProj(DMODEL / 128, MTOT / 128);          // (8, 64)
    out_proj_kernel<<<gProj, 256>>>(Wo, bo, out);
}

// round 14
// speedup vs baseline: 1.5324x; 1.5324x over previous
// R14: tcgen05 is DEAD on this harness (ptxas targets compute_103, not
// sm_103a — R13 evidence). Re-target the split-bf16 projection GEMMs to
// baseline-PTX mma.sync m16n8k16 + ldmatrix (sm_80+, compiles anywhere).
// Attention unchanged. Fallback = R10 @ 4160us.
#include <cuda_runtime.h>
#include <cuda_bf16.h>

#define BATCH   4
#define SEQ     2048
#define DMODEL  1024
#define NHEAD   16
#define DK      64
#define MTOT    (BATCH * SEQ)   // 8192
#define DD      (DMODEL * DMODEL)

// ---------------------------------------------------------------------------
// Device-global scratch (allocation-free rule)
// ---------------------------------------------------------------------------
__device__ float g_Q[(size_t)BATCH * NHEAD * SEQ * DK];   // [b,h,s,d] fp32
__device__ float g_K[(size_t)BATCH * NHEAD * SEQ * DK];
__device__ float g_V[(size_t)BATCH * NHEAD * SEQ * DK];
__device__ float g_O[(size_t)MTOT * DMODEL];              // [b,s,h*64+d] fp32

__device__ __nv_bfloat16 g_xhi[(size_t)MTOT * DMODEL];
__device__ __nv_bfloat16 g_xlo[(size_t)MTOT * DMODEL];
__device__ __nv_bfloat16 g_Whi[(size_t)4 * DD];           // Wq,Wk,Wv,Wo
__device__ __nv_bfloat16 g_Wlo[(size_t)4 * DD];
__device__ __nv_bfloat16 g_ohi[(size_t)MTOT * DMODEL];
__device__ __nv_bfloat16 g_olo[(size_t)MTOT * DMODEL];

// ---------------------------------------------------------------------------
// Warp-level bf16 MMA helpers (baseline PTX: sm_80+, safe on compute_103)
// ---------------------------------------------------------------------------
__device__ __forceinline__ unsigned smem_u32(const void* p) {
    unsigned a;
    asm("{ .reg .u64 t; cvta.to.shared.u64 t, %1; cvt.u32.u64 %0, t; }"
        : "=r"(a) : "l"(p));
    return a;
}

__device__ __forceinline__ void ldmat4(unsigned addr,
                                       unsigned& r0, unsigned& r1,
                                       unsigned& r2, unsigned& r3) {
    asm volatile("ldmatrix.sync.aligned.m8n8.x4.shared.b16 {%0,%1,%2,%3}, [%4];"
        : "=r"(r0), "=r"(r1), "=r"(r2), "=r"(r3) : "r"(addr));
}

__device__ __forceinline__ void mma16816(float* d, const unsigned* a,
                                         unsigned b0, unsigned b1) {
    asm volatile(
        "mma.sync.aligned.m16n8k16.row.col.f32.bf16.bf16.f32 "
        "{%0,%1,%2,%3}, {%4,%5,%6,%7}, {%8,%9}, {%0,%1,%2,%3};"
        : "+f"(d[0]), "+f"(d[1]), "+f"(d[2]), "+f"(d[3])
        : "r"(a[0]), "r"(a[1]), "r"(a[2]), "r"(a[3]), "r"(b0), "r"(b1));
}

// Tile geometry: CTA 128x128, K-chunk 32, 8 warps as 2(M) x 4(N), warp 64x32.
#define KC   32
#define LDS_PAD 40   // bf16 row stride (80B): ldmatrix rows hit distinct bank quads

// C[128x128] += sum_K (Ah*Bh^T + Ah*Bl^T + Al*Bh^T). A,B row-major [*,1024].
// acc[i][j][4]: m-frag i (16 rows), n-frag j (8 cols).
__device__ __forceinline__ void mma_gemm_128(
    const __nv_bfloat16* __restrict__ Ahi, const __nv_bfloat16* __restrict__ Alo,
    const __nv_bfloat16* __restrict__ Bhi, const __nv_bfloat16* __restrict__ Blo,
    int m0, int n0, float acc[4][4][4])
{
    __shared__ __nv_bfloat16 Ah_s[128][LDS_PAD], Al_s[128][LDS_PAD];
    __shared__ __nv_bfloat16 Bh_s[128][LDS_PAD], Bl_s[128][LDS_PAD];

    const int tid  = threadIdx.x;
    const int lane = tid & 31, wid = tid >> 5;
    const int wy = wid & 1, wx = wid >> 1;      // warp m/n position
    const int mbase = wy * 64, nbase = wx * 32;

    // ldmatrix per-lane row/col offsets
    const int seg = lane >> 3, lr = lane & 7;
    const int a_row_off = lr + (seg & 1) * 8;   // + i*16 + mbase
    const int a_col_off = (seg >> 1) * 8;       // + ks
    const int b_row_off = lr + (seg >> 1) * 8;  // + jp*16 + nbase
    const int b_col_off = (seg & 1) * 8;        // + ks

    for (int ch = 0; ch < DMODEL / KC; ch++) {
        const int k0 = ch * KC;
        // Load 4 tiles of 128x32 bf16 (2 x 16B per thread per tile, coalesced)
        __syncthreads();
#pragma unroll
        for (int t = 0; t < 2; t++) {
            int idx = t * 256 + tid;            // 0..511
            int row = idx >> 2, sg = idx & 3;   // col = sg*8
            const size_t go = (size_t)row * DMODEL + k0 + sg * 8;
            *reinterpret_cast<uint4*>(&Ah_s[row][sg * 8]) =
                *reinterpret_cast<const uint4*>(Ahi + (size_t)(m0) * DMODEL + go);
            *reinterpret_cast<uint4*>(&Al_s[row][sg * 8]) =
                *reinterpret_cast<const uint4*>(Alo + (size_t)(m0) * DMODEL + go);
            *reinterpret_cast<uint4*>(&Bh_s[row][sg * 8]) =
                *reinterpret_cast<const uint4*>(Bhi + (size_t)(n0) * DMODEL + go);
            *reinterpret_cast<uint4*>(&Bl_s[row][sg * 8]) =
                *reinterpret_cast<const uint4*>(Blo + (size_t)(n0) * DMODEL + go);
        }
        __syncthreads();

#pragma unroll
        for (int ks = 0; ks < KC; ks += 16) {
            // B fragments: two x4 loads cover 4 n-frags (hi), two more (lo)
            unsigned bh[2][4], bl[2][4];
#pragma unroll
            for (int jp = 0; jp < 2; jp++) {
                unsigned ba = smem_u32(&Bh_s[nbase + jp * 16 + b_row_off][ks + b_col_off]);
                ldmat4(ba, bh[jp][0], bh[jp][1], bh[jp][2], bh[jp][3]);
                unsigned bb = smem_u32(&Bl_s[nbase + jp * 16 + b_row_off][ks + b_col_off]);
                ldmat4(bb, bl[jp][0], bl[jp][1], bl[jp][2], bl[jp][3]);
            }
#pragma unroll
            for (int i = 0; i < 4; i++) {
                unsigned ah[4], al[4];
                unsigned aa = smem_u32(&Ah_s[mbase + i * 16 + a_row_off][ks + a_col_off]);
                ldmat4(aa, ah[0], ah[1], ah[2], ah[3]);
                unsigned ab = smem_u32(&Al_s[mbase + i * 16 + a_row_off][ks + a_col_off]);
                ldmat4(ab, al[0], al[1], al[2], al[3]);
#pragma unroll
                for (int j = 0; j < 4; j++) {
                    const int jp = j >> 1, jh = (j & 1) * 2;
                    mma16816(acc[i][j], ah, bh[jp][jh], bh[jp][jh + 1]);
                    mma16816(acc[i][j], ah, bl[jp][jh], bl[jp][jh + 1]);
                    mma16816(acc[i][j], al, bh[jp][jh], bh[jp][jh + 1]);
                }
            }
        }
    }
}

// ---------------------------------------------------------------------------
// fp32 -> bf16 hi/lo split
// ---------------------------------------------------------------------------
__global__ void __launch_bounds__(256)
split_kernel(const float* __restrict__ src, __nv_bfloat16* __restrict__ hi,
             __nv_bfloat16* __restrict__ lo, int n4)
{
    int i = blockIdx.x * 256 + threadIdx.x;
    if (i >= n4) return;
    float4 v = reinterpret_cast<const float4*>(src)[i];
    __nv_bfloat16 h0 = __float2bfloat16_rn(v.x);
    __nv_bfloat16 h1 = __float2bfloat16_rn(v.y);
    __nv_bfloat16 h2 = __float2bfloat16_rn(v.z);
    __nv_bfloat16 h3 = __float2bfloat16_rn(v.w);
    __nv_bfloat16 l0 = __float2bfloat16_rn(v.x - __bfloat162float(h0));
    __nv_bfloat16 l1 = __float2bfloat16_rn(v.y - __bfloat162float(h1));
    __nv_bfloat16 l2 = __float2bfloat16_rn(v.z - __bfloat162float(h2));
    __nv_bfloat16 l3 = __float2bfloat16_rn(v.w - __bfloat162float(h3));
    ushort4 H = make_ushort4(__bfloat16_as_ushort(h0), __bfloat16_as_ushort(h1),
                             __bfloat16_as_ushort(h2), __bfloat16_as_ushort(h3));
    ushort4 L = make_ushort4(__bfloat16_as_ushort(l0), __bfloat16_as_ushort(l1),
                             __bfloat16_as_ushort(l2), __bfloat16_as_ushort(l3));
    reinterpret_cast<ushort4*>(hi)[i] = H;
    reinterpret_cast<ushort4*>(lo)[i] = L;
}

// ---------------------------------------------------------------------------
// Tensor-core QKV projection: grid (8, 64, 3)
// ---------------------------------------------------------------------------
__global__ void __launch_bounds__(256, 2)
tc_qkv_kernel(const float* __restrict__ bq, const float* __restrict__ bk,
              const float* __restrict__ bv)
{
    const int z = blockIdx.z;
    const int m0 = blockIdx.y * 128, n0 = blockIdx.x * 128;

    float acc[4][4][4];
#pragma unroll
    for (int i = 0; i < 4; i++)
#pragma unroll
        for (int j = 0; j < 4; j++) {
            acc[i][j][0] = 0.f; acc[i][j][1] = 0.f;
            acc[i][j][2] = 0.f; acc[i][j][3] = 0.f;
        }

    mma_gemm_128(g_xhi, g_xlo,
                 g_Whi + (size_t)z * DD, g_Wlo + (size_t)z * DD,
                 m0, n0, acc);

    const float* bias = (z == 0) ? bq : ((z == 1) ? bk : bv);
    float* out        = (z == 0) ? g_Q : ((z == 1) ? g_K : g_V);

    const int lane = threadIdx.x & 31, wid = threadIdx.x >> 5;
    const int wy = wid & 1, wx = wid >> 1;
#pragma unroll
    for (int i = 0; i < 4; i++) {
#pragma unroll
        for (int j = 0; j < 4; j++) {
            int n = n0 + wx * 32 + j * 8 + (lane & 3) * 2;
            int h = n >> 6, d = n & 63;
            float b0 = bias[n], b1 = bias[n + 1];
#pragma unroll
            for (int hrow = 0; hrow < 2; hrow++) {
                int m = m0 + wy * 64 + i * 16 + (lane >> 2) + hrow * 8;
                int bb = m >> 11, s = m & 2047;
                float2 val = make_float2(acc[i][j][hrow * 2] + b0,
                                         acc[i][j][hrow * 2 + 1] + b1);
                *reinterpret_cast<float2*>(
                    &out[((size_t)(bb * NHEAD + h) * SEQ + s) * DK + d]) = val;
            }
        }
    }
}

// ---------------------------------------------------------------------------
// Tensor-core output projection: grid (8, 64)
// ---------------------------------------------------------------------------
__global__ void __launch_bounds__(256, 2)
tc_out_kernel(const float* __restrict__ bo, float* __restrict__ outp)
{
    const int m0 = blockIdx.y * 128, n0 = blockIdx.x * 128;

    float acc[4][4][4];
#pragma unroll
    for (int i = 0; i < 4; i++)
#pragma unroll
        for (int j = 0; j < 4; j++) {
            acc[i][j][0] = 0.f; acc[i][j][1] = 0.f;
            acc[i][j][2] = 0.f; acc[i][j][3] = 0.f;
        }

    mma_gemm_128(g_ohi, g_olo,
                 g_Whi + (size_t)3 * DD, g_Wlo + (size_t)3 * DD,
                 m0, n0, acc);

    const int lane = threadIdx.x & 31, wid = threadIdx.x >> 5;
    const int wy = wid & 1, wx = wid >> 1;
#pragma unroll
    for (int i = 0; i < 4; i++) {
#pragma unroll
        for (int j = 0; j < 4; j++) {
            int n = n0 + wx * 32 + j * 8 + (lane & 3) * 2;
            float b0 = bo[n], b1 = bo[n + 1];
#pragma unroll
            for (int hrow = 0; hrow < 2; hrow++) {
                int m = m0 + wy * 64 + i * 16 + (lane >> 2) + hrow * 8;
                float2 val = make_float2(acc[i][j][hrow * 2] + b0,
                                         acc[i][j][hrow * 2 + 1] + b1);
                *reinterpret_cast<float2*>(&outp[(size_t)m * DMODEL + n]) = val;
            }
        }
    }
}

// ---------------------------------------------------------------------------
// Flash attention — UNCHANGED from the passing R10 baseline.
// ---------------------------------------------------------------------------
__global__ __launch_bounds__(256)
void attn_kernel()
{
    const int bh = blockIdx.y;
    const int q0 = blockIdx.x * 64;
    const float* Qp = g_Q + (size_t)bh * SEQ * DK;
    const float* Kp = g_K + (size_t)bh * SEQ * DK;
    const float* Vp = g_V + (size_t)bh * SEQ * DK;

    __shared__ float Qs[64][64];
    __shared__ float Ks[32][68];
    __shared__ float Vs[32][64];
    __shared__ float Ps[64][32];

    const int tid = threadIdx.x;
    const int tx = tid & 15, ty = tid >> 4;

#pragma unroll
    for (int t = 0; t < 4; t++) {
        int idx = tid + t * 256;
        int row = idx >> 4, cq = (idx & 15) * 4;
        float4 q = *reinterpret_cast<const float4*>(Qp + (size_t)(q0 + row) * DK + cq);
        q.x *= 0.125f; q.y *= 0.125f; q.z *= 0.125f; q.w *= 0.125f;
        *reinterpret_cast<float4*>(&Qs[row][cq]) = q;
    }

    float m_i[4], l_i[4], o[4][4];
#pragma unroll
    for (int i = 0; i < 4; i++) {
        m_i[i] = -1e30f; l_i[i] = 0.0f;
#pragma unroll
        for (int j = 0; j < 4; j++) o[i][j] = 0.0f;
    }

    float4 pk[2], pv[2];
#pragma unroll
    for (int t = 0; t < 2; t++) {
        int idx = tid + t * 256;
        int row = idx >> 4, cq = (idx & 15) * 4;
        pk[t] = *reinterpret_cast<const float4*>(Kp + (size_t)row * DK + cq);
        pv[t] = *reinterpret_cast<const float4*>(Vp + (size_t)row * DK + cq);
    }

    for (int kt = 0; kt < SEQ; kt += 32) {
        __syncthreads();
#pragma unroll
        for (int t = 0; t < 2; t++) {
            int idx = tid + t * 256;
            int row = idx >> 4, cq = (idx & 15) * 4;
            *reinterpret_cast<float4*>(&Ks[row][cq]) = pk[t];
            *reinterpret_cast<float4*>(&Vs[row][cq]) = pv[t];
        }
        __syncthreads();

        if (kt + 32 < SEQ) {
#pragma unroll
            for (int t = 0; t < 2; t++) {
                int idx = tid + t * 256;
                int row = idx >> 4, cq = (idx & 15) * 4;
                pk[t] = *reinterpret_cast<const float4*>(Kp + (size_t)(kt + 32 + row) * DK + cq);
                pv[t] = *reinterpret_cast<const float4*>(Vp + (size_t)(kt + 32 + row) * DK + cq);
            }
        }

        float s[4][2];
#pragma unroll
        for (int i = 0; i < 4; i++) { s[i][0] = 0.0f; s[i][1] = 0.0f; }
#pragma unroll
        for (int kk = 0; kk < 64; kk += 4) {
            float4 b0 = *reinterpret_cast<const float4*>(&Ks[tx][kk]);
            float4 b1 = *reinterpret_cast<const float4*>(&Ks[16 + tx][kk]);
#pragma unroll
            for (int i = 0; i < 4; i++) {
                float4 a = *reinterpret_cast<const float4*>(&Qs[i * 16 + ty][kk]);
                s[i][0] = fmaf(a.x, b0.x, s[i][0]);
                s[i][0] = fmaf(a.y, b0.y, s[i][0]);
                s[i][0] = fmaf(a.z, b0.z, s[i][0]);
                s[i][0] = fmaf(a.w, b0.w, s[i][0]);
                s[i][1] = fmaf(a.x, b1.x, s[i][1]);
                s[i][1] = fmaf(a.y, b1.y, s[i][1]);
                s[i][1] = fmaf(a.z, b1.z, s[i][1]);
                s[i][1] = fmaf(a.w, b1.w, s[i][1]);
            }
        }

#pragma unroll
        for (int i = 0; i < 4; i++) {
            float s0 = s[i][0];
            float s1 = s[i][1];
            float rm = fmaxf(s0, s1);
#pragma unroll
            for (int off = 1; off < 16; off <<= 1)
                rm = fmaxf(rm, __shfl_xor_sync(0xffffffffu, rm, off, 16));
            float mn = fmaxf(m_i[i], rm);
            float corr = __expf(m_i[i] - mn);
            float p0 = __expf(s0 - mn);
            float p1 = __expf(s1 - mn);
            float rs = p0 + p1;
#pragma unroll
            for (int off = 1; off < 16; off <<= 1)
                rs += __shfl_xor_sync(0xffffffffu, rs, off, 16);
            l_i[i] = l_i[i] * corr + rs;
            m_i[i] = mn;
#pragma unroll
            for (int j = 0; j < 4; j++) o[i][j] *= corr;
            Ps[i * 16 + ty][tx]      = p0;
            Ps[i * 16 + ty][16 + tx] = p1;
        }
        __syncthreads();

#pragma unroll
        for (int kk4 = 0; kk4 < 32; kk4 += 4) {
            float4 p4[4];
#pragma unroll
            for (int i = 0; i < 4; i++)
                p4[i] = *reinterpret_cast<const float4*>(&Ps[i * 16 + ty][kk4]);
#pragma unroll
            for (int u = 0; u < 4; u++) {
                float4 v4 = *reinterpret_cast<const float4*>(&Vs[kk4 + u][tx * 4]);
                float p[4] = {
                    reinterpret_cast<const float*>(&p4[0])[u],
                    reinterpret_cast<const float*>(&p4[1])[u],
                    reinterpret_cast<const float*>(&p4[2])[u],
                    reinterpret_cast<const float*>(&p4[3])[u]
                };
#pragma unroll
                for (int i = 0; i < 4; i++) {
                    o[i][0] = fmaf(p[i], v4.x, o[i][0]);
                    o[i][1] = fmaf(p[i], v4.y, o[i][1]);
                    o[i][2] = fmaf(p[i], v4.z, o[i][2]);
                    o[i][3] = fmaf(p[i], v4.w, o[i][3]);
                }
            }
        }
    }

    const int b = bh >> 4, h = bh & 15;
#pragma unroll
    for (int i = 0; i < 4; i++) {
        float inv = 1.0f / l_i[i];
        int srow = q0 + i * 16 + ty;
        float4 val = make_float4(o[i][0] * inv, o[i][1] * inv,
                                 o[i][2] * inv, o[i][3] * inv);
        *reinterpret_cast<float4*>(
            &g_O[((size_t)(b * SEQ + srow)) * DMODEL + h * DK + tx * 4]) = val;
    }
}

// ---------------------------------------------------------------------------
extern "C" void kernel_launch(void* const* d_in, const int* in_sizes, int n_in,
                              void* d_out, int out_size)
{
    const float* x  = (const float*)d_in[0];
    const float* Wq = (const float*)d_in[1];
    const float* bq = (const float*)d_in[2];
    const float* Wk = (const float*)d_in[3];
    const float* bk = (const float*)d_in[4];
    const float* Wv = (const float*)d_in[5];
    const float* bv = (const float*)d_in[6];
    const float* Wo = (const float*)d_in[7];
    const float* bo = (const float*)d_in[8];
    float* out = (float*)d_out;

    void *xhi, *xlo, *whi, *wlo, *op, *ohi, *olo;
    cudaGetSymbolAddress(&xhi, g_xhi);
    cudaGetSymbolAddress(&xlo, g_xlo);
    cudaGetSymbolAddress(&whi, g_Whi);
    cudaGetSymbolAddress(&wlo, g_Wlo);
    cudaGetSymbolAddress(&op,  g_O);
    cudaGetSymbolAddress(&ohi, g_ohi);
    cudaGetSymbolAddress(&olo, g_olo);

    const int nX4 = MTOT * DMODEL / 4;
    const int nW4 = DD / 4;
    split_kernel<<<(nX4 + 255) / 256, 256>>>(x,  (__nv_bfloat16*)xhi, (__nv_bfloat16*)xlo, nX4);
    split_kernel<<<(nW4 + 255) / 256, 256>>>(Wq, (__nv_bfloat16*)whi + 0 * (size_t)DD, (__nv_bfloat16*)wlo + 0 * (size_t)DD, nW4);
    split_kernel<<<(nW4 + 255) / 256, 256>>>(Wk, (__nv_bfloat16*)whi + 1 * (size_t)DD, (__nv_bfloat16*)wlo + 1 * (size_t)DD, nW4);
    split_kernel<<<(nW4 + 255) / 256, 256>>>(Wv, (__nv_bfloat16*)whi + 2 * (size_t)DD, (__nv_bfloat16*)wlo + 2 * (size_t)DD, nW4);
    split_kernel<<<(nW4 + 255) / 256, 256>>>(Wo, (__nv_bfloat16*)whi + 3 * (size_t)DD, (__nv_bfloat16*)wlo + 3 * (size_t)DD, nW4);

    tc_qkv_kernel<<<dim3(DMODEL / 128, MTOT / 128, 3), 256>>>(bq, bk, bv);

    attn_kernel<<<dim3(SEQ / 64, BATCH * NHEAD), 256>>>();

    split_kernel<<<(nX4 + 255) / 256, 256>>>((const float*)op, (__nv_bfloat16*)ohi, (__nv_bfloat16*)olo, nX4);

    tc_out_kernel<<<dim3(DMODEL / 128, MTOT / 128), 256>>>(bo, out);
}